// round 7
// baseline (speedup 1.0000x reference)
#include <cuda_runtime.h>
#include <cuda_fp16.h>
#include <math.h>
#include <stdint.h>

// ---------------- problem constants ----------------
#define NS    16384
#define DIMX  3200
#define LMAX  4

__constant__ int c_offD[4] = {0, 9, 34, 83};

// 13 sub-GEMMs: 0: m0 (640x640); then per m=1..4: A, B, A+B (co x co)
__constant__ int cg_tileStart[14] = {0,640,1152,1664,2176,2560,2944,3328,3584,3840,4096,4224,4352,4480};
__constant__ int cg_Ksub[13]  = {640,512,512,512,384,384,384,256,256,256,128,128,128};
__constant__ int cg_UZp[13]   = {0,640,1152,1664,2176,2560,2944,3328,3584,3840,4096,4224,4352};
__constant__ int cg_Wpref[14] = {0,409600,671744,933888,1196032,1343488,1490944,1638400,1703936,1769472,1835008,1851392,1867776,1884160};

// ---------------- device scratch ----------------
__device__ float g_J[164];
__device__ float g_DT[(size_t)NS * 164];
__device__ __half g_W[1884160];
__device__ __half g_U[(size_t)NS * 4480];
__device__ float g_Z[(size_t)NS * 4480];

// =======================================================================
// Kernel 0: build J matrices (reference algorithm, fp64, parallel)
// =======================================================================
__global__ void build_J_kernel() {
    __shared__ double Xr[4][81], Xi[4][81], Qr[4][81], Qi[4][81];
    __shared__ double Sa[4][81], Se[4][81], St[4][81];
    int g = threadIdx.x / 96;
    int e = threadIdx.x % 96;
    int l = g + 1, d = 2*l + 1, dd = d*d;
    const double j = (double)l;
    const double SQ12 = 0.70710678118654752440;
    const double PI_D = 3.14159265358979323846;

    if (e < 81) { Xr[g][e]=0; Xi[g][e]=0; Qr[g][e]=0; Qi[g][e]=0; }
    __syncthreads();
    if (e == 0) {
        for (int i2 = 0; i2 < d-1; i2++) {
            double m  = -j + (double)i2;
            double rv = -sqrt(j*(j+1.0) - m*(m+1.0));
            Xr[g][(i2+1)*d + i2] += 0.5 * rv;
            double m2 = -j + 1.0 + (double)i2;
            double lv = sqrt(j*(j+1.0) - m2*(m2-1.0));
            Xr[g][i2*d + (i2+1)] += 0.5 * lv;
        }
        for (int i2 = 0; i2 < d; i2++) Xi[g][i2*d + i2] += (-j + (double)i2);
        for (int m = 1; m <= l; m++) {
            int r = l - m;
            Qr[g][r*d + (l+m)] = SQ12;
            Qi[g][r*d + r]     = -SQ12;
            int r2 = l + m;
            double sgn = (m & 1) ? -1.0 : 1.0;
            Qr[g][r2*d + r2]     = sgn * SQ12;
            Qi[g][r2*d + (l-m)]  = sgn * SQ12;
        }
        Qr[g][l*d + l] = 1.0;
    }
    __syncthreads();
    if (e < dd) {
        int i = e / d, jj = e % d;
        double s = 0.0;
        for (int k = 0; k < d; k++) {
            double mr = 0.0, mi = 0.0;
            for (int p = 0; p < d; p++) {
                mr += Xr[g][k*d+p]*Qr[g][p*d+jj] - Xi[g][k*d+p]*Qi[g][p*d+jj];
                mi += Xr[g][k*d+p]*Qi[g][p*d+jj] + Xi[g][k*d+p]*Qr[g][p*d+jj];
            }
            s += Qr[g][k*d+i]*mr + Qi[g][k*d+i]*mi;
        }
        Sa[g][e] = (PI_D * SQ12) * s * (1.0/1024.0);
        Se[g][e] = (i == jj) ? 1.0 : 0.0;
        St[g][e] = (i == jj) ? 1.0 : 0.0;
    }
    __syncthreads();
    for (int k = 1; k < 24; k++) {
        double v = 0.0;
        if (e < dd) {
            int i = e / d, jj = e % d;
            double s = 0.0;
            for (int p = 0; p < d; p++) s += St[g][i*d+p] * Sa[g][p*d+jj];
            v = s / (double)k;
        }
        __syncthreads();
        if (e < dd) { St[g][e] = v; Se[g][e] += v; }
        __syncthreads();
    }
    for (int s2 = 0; s2 < 10; s2++) {
        double v = 0.0;
        if (e < dd) {
            int i = e / d, jj = e % d;
            double s = 0.0;
            for (int p = 0; p < d; p++) s += Se[g][i*d+p] * Se[g][p*d+jj];
            v = s;
        }
        __syncthreads();
        if (e < dd) Se[g][e] = v;
        __syncthreads();
    }
    if (e < dd) g_J[c_offD[g] + e] = (float)Se[g][e];
}

// =======================================================================
// Kernel 1: build W (fp16): sub 0 = fc0_w; subs 3m-2..3m: A, B, A+B
// =======================================================================
__global__ void build_w_kernel(const float* __restrict__ fc0_w,
                               const float* __restrict__ w1, const float* __restrict__ w2,
                               const float* __restrict__ w3, const float* __restrict__ w4) {
    int gid = blockIdx.x * blockDim.x + threadIdx.x;
    if (gid >= 1884160) return;
    int s = 0;
    #pragma unroll
    for (int q = 1; q < 13; q++) if (gid >= cg_Wpref[q]) s = q;
    int local = gid - cg_Wpref[s];
    int K = cg_Ksub[s];
    int o = local / K;
    int t = local - o * K;
    float v;
    if (s == 0) {
        v = fc0_w[o * 640 + t];
    } else {
        int m = (s - 1) / 3 + 1;
        int which = (s - 1) % 3;
        const float* w = (m == 1) ? w1 : (m == 2) ? w2 : (m == 3) ? w3 : w4;
        if (which == 0)      v = w[o * K + t];
        else if (which == 1) v = w[(K + o) * K + t];
        else                 v = w[o * K + t] + w[(K + o) * K + t];
    }
    g_W[gid] = __float2half_rn(v);
}

// =======================================================================
// Kernel 2: per-sample Wigner D^T (D = Z(a) J Z(b) J)
// =======================================================================
__global__ void wigner_kernel(const float* __restrict__ R) {
    int gid = blockIdx.x * blockDim.x + threadIdx.x;
    if (gid >= NS * 4) return;
    int n = gid >> 2;
    int l = (gid & 3) + 1;
    int d = 2*l + 1;

    float vx = R[n*3 + 1], vy = R[n*3 + 2], vz = R[n*3 + 0];
    float nrm = sqrtf(vx*vx + vy*vy + vz*vz);
    nrm = fmaxf(nrm, 1e-12f);
    vx /= nrm; vy /= nrm; vz /= nrm;
    vx = fminf(fmaxf(vx, -1.f), 1.f);
    vy = fminf(fmaxf(vy, -1.f), 1.f);
    vz = fminf(fmaxf(vz, -1.f), 1.f);
    float beta  = acosf(vy);
    float alpha = atan2f(vx, vz);

    const float* J = g_J + c_offD[l-1];
    float T1[81], T2[81], Dm[81];

    for (int i = 0; i < d; i++) {
        float fr = (float)(l - i);
        float c = cosf(fr * beta), s = sinf(fr * beta);
        int ri = d - 1 - i;
        for (int jj = 0; jj < d; jj++)
            T1[i*d + jj] = c * J[i*d + jj] + s * J[ri*d + jj];
    }
    for (int i = 0; i < d; i++)
        for (int jj = 0; jj < d; jj++) {
            float s = 0.f;
            for (int k = 0; k < d; k++) s += J[i*d + k] * T1[k*d + jj];
            T2[i*d + jj] = s;
        }
    for (int i = 0; i < d; i++) {
        float fr = (float)(l - i);
        float c = cosf(fr * alpha), s = sinf(fr * alpha);
        int ri = d - 1 - i;
        for (int jj = 0; jj < d; jj++)
            Dm[i*d + jj] = c * T2[i*d + jj] + s * T2[ri*d + jj];
    }
    float* dst = g_DT + (size_t)n * 164 + c_offD[l-1];
    for (int i = 0; i < d; i++)
        for (int jj = 0; jj < d; jj++)
            dst[i*d + jj] = Dm[jj*d + i];
}

// =======================================================================
// Kernel 3: rotate x (block-per-thread), gather into fp16 sub-GEMM inputs
// =======================================================================
__global__ __launch_bounds__(256) void rot_gather_kernel(const float* __restrict__ x) {
    int n = blockIdx.x;
    __shared__ float xs[DIMX];
    __shared__ float xrot[DIMX];
    __shared__ float dt[164];
    const float* xr = x + (size_t)n * DIMX;
    for (int c = threadIdx.x; c < DIMX; c += 256) xs[c] = xr[c];
    for (int c = threadIdx.x; c < 164; c += 256) dt[c] = g_DT[(size_t)n * 164 + c];
    __syncthreads();

    // phase 1: block-per-thread rotation. k = tid&127; half 0: l=1,4; half 1: l=2,3
    int k = threadIdx.x & 127;
    int h = threadIdx.x >> 7;
    #define ROTBLK(D, DTO, XO) do {                                          \
        const float* xb = xs + XO + k * D;                                   \
        float xv[D];                                                         \
        _Pragma("unroll") for (int j = 0; j < D; j++) xv[j] = xb[j];         \
        _Pragma("unroll") for (int i = 0; i < D; i++) {                      \
            const float* ddp = dt + DTO + i * D;                             \
            float v = 0.f;                                                   \
            _Pragma("unroll") for (int j = 0; j < D; j++) v += ddp[j] * xv[j]; \
            xrot[XO + k * D + i] = v;                                        \
        }                                                                    \
    } while (0)
    if (h == 0) { ROTBLK(3, 0, 128);  ROTBLK(9, 83, 2048); }
    else        { ROTBLK(5, 9, 512);  ROTBLK(7, 34, 1152); }
    __syncthreads();

    // phase 2: gather into U
    for (int j = threadIdx.x; j < 640; j += 256) {
        int l = j >> 7, kk = j & 127;
        float v = (l == 0) ? 0.f : xrot[128*l*l + kk*(2*l + 1) + l];
        g_U[(size_t)n * 640 + j] = __float2half_rn(v);
    }
    #define GATH(MM, CO, P0, P1, P2)                                         \
    for (int t = threadIdx.x; t < CO; t += 256) {                            \
        int c0 = t & 1, ph = t >> 1;                                         \
        int p1 = (CO >> 1) + ph;                                             \
        int l0 = MM + (ph >> 7), k0 = ph & 127;                              \
        int l1 = MM + (p1 >> 7), k1 = p1 & 127;                              \
        int i0 = c0 ? (l0 + MM) : (l0 - MM);                                 \
        int i1 = c0 ? (l1 + MM) : (l1 - MM);                                 \
        float u0 = xrot[128*l0*l0 + k0*(2*l0 + 1) + i0];                     \
        float u1 = xrot[128*l1*l1 + k1*(2*l1 + 1) + i1];                     \
        g_U[(size_t)NS * P0 + (size_t)n * CO + t] = __float2half_rn(u0);     \
        g_U[(size_t)NS * P1 + (size_t)n * CO + t] = __float2half_rn(u1);     \
        g_U[(size_t)NS * P2 + (size_t)n * CO + t] = __float2half_rn(u0 + u1);\
    }
    GATH(1, 512, 640, 1152, 1664)
    GATH(2, 384, 2176, 2560, 2944)
    GATH(3, 256, 3328, 3584, 3840)
    GATH(4, 128, 4096, 4224, 4352)
}

// =======================================================================
// Kernel 4: HMMA fp16 GEMM over 13 sub-GEMMs
// =======================================================================
__device__ __forceinline__ uint32_t smem_u32(const void* p) {
    uint32_t a;
    asm("{ .reg .u64 t; cvta.to.shared.u64 t, %1; cvt.u32.u64 %0, t; }" : "=r"(a) : "l"(p));
    return a;
}
#define CP_ASYNC16(dst, src) \
    asm volatile("cp.async.cg.shared.global [%0], [%1], 16;" :: "r"(dst), "l"(src) : "memory")
#define CP_COMMIT() asm volatile("cp.async.commit_group;" ::: "memory")
#define CP_WAIT1()  asm volatile("cp.async.wait_group 1;" ::: "memory")
#define CP_WAIT0()  asm volatile("cp.async.wait_group 0;" ::: "memory")
#define LDSM_X4(r0, r1, r2, r3, addr) \
    asm volatile("ldmatrix.sync.aligned.m8n8.x4.shared.b16 {%0,%1,%2,%3}, [%4];" \
                 : "=r"(r0), "=r"(r1), "=r"(r2), "=r"(r3) : "r"(addr))

__device__ __forceinline__ void hmma16816(float* c, const uint32_t* a, const uint32_t* b) {
    asm volatile(
        "mma.sync.aligned.m16n8k16.row.col.f32.f16.f16.f32 "
        "{%0,%1,%2,%3}, {%4,%5,%6,%7}, {%8,%9}, {%0,%1,%2,%3};"
        : "+f"(c[0]), "+f"(c[1]), "+f"(c[2]), "+f"(c[3])
        : "r"(a[0]), "r"(a[1]), "r"(a[2]), "r"(a[3]), "r"(b[0]), "r"(b[1]));
}

__global__ __launch_bounds__(256, 2) void hmma_gemm_all_kernel() {
    extern __shared__ __align__(1024) char dsm[];
    uint32_t sbase = smem_u32(dsm);

    int tid = threadIdx.x;
    int wid = tid >> 5;
    int lane = tid & 31;

    // ---- tile decode ----
    int id = blockIdx.x;
    int s = 0;
    #pragma unroll
    for (int q = 1; q < 13; q++) if (id >= cg_tileStart[q]) s = q;
    int local = id - cg_tileStart[s];
    int K = cg_Ksub[s];
    int gx = K >> 7;
    int bcolt = local % gx, browt = local / gx;
    int brow = browt << 7, bcol = bcolt << 7;

    const __half* A = g_U + (size_t)NS * cg_UZp[s];
    const __half* B = g_W + cg_Wpref[s];
    float* C = g_Z + (size_t)NS * cg_UZp[s];

    // ---- global->smem: 2 threads/row, 4x16B each ----
    int r = tid >> 1, q2 = tid & 1;
    const char* gA = (const char*)(A + (size_t)(brow + r) * K + q2 * 32);
    const char* gB = (const char*)(B + (size_t)(bcol + r) * K + q2 * 32);
    uint32_t sts[4];
    #pragma unroll
    for (int i = 0; i < 4; i++) {
        uint32_t off = (uint32_t)r * 128u + (uint32_t)(q2 * 4 + i) * 16u;
        sts[i] = off ^ ((off >> 3) & 0x70);
    }

    // ---- per-warp compute layout ----
    int wm = wid >> 1, wn = wid & 1;
    uint32_t a_row[2], a_rx[2];
    #pragma unroll
    for (int mt = 0; mt < 2; mt++) {
        int row = wm * 32 + mt * 16 + (lane & 15);
        a_row[mt] = (uint32_t)row * 128u;
        a_rx[mt] = (uint32_t)(row & 7) << 4;
    }
    uint32_t a_cb = ((lane >> 4) & 1) * 16u;
    int nloc = (lane & 7) + ((lane & 16) >> 1);
    uint32_t b_row[4], b_rx[4];
    #pragma unroll
    for (int nt4 = 0; nt4 < 4; nt4++) {
        int nrow = wn * 64 + nt4 * 16 + nloc;
        b_row[nt4] = (uint32_t)nrow * 128u;
        b_rx[nt4] = (uint32_t)(nrow & 7) << 4;
    }
    uint32_t b_cb = ((lane >> 3) & 1) * 16u;

    float acc[2][8][4];
    #pragma unroll
    for (int mt = 0; mt < 2; mt++)
        #pragma unroll
        for (int nt = 0; nt < 8; nt++)
            #pragma unroll
            for (int e = 0; e < 4; e++) acc[mt][nt][e] = 0.f;

    int NC = K >> 6;

    // prologue: chunks 0,1 into stages 0,1
    #pragma unroll
    for (int p = 0; p < 2; p++) {
        uint32_t aS = sbase + (uint32_t)p * 32768u;
        uint32_t bS = aS + 16384u;
        const char* Ap = gA + (size_t)p * 128;
        const char* Bp = gB + (size_t)p * 128;
        #pragma unroll
        for (int i = 0; i < 4; i++) {
            CP_ASYNC16(aS + sts[i], Ap + i * 16);
            CP_ASYNC16(bS + sts[i], Bp + i * 16);
        }
        CP_COMMIT();
    }

    for (int c = 0; c < NC; ++c) {
        if (c + 1 < NC) CP_WAIT1(); else CP_WAIT0();
        __syncthreads();
        if (c + 2 < NC) {
            int st = (c + 2) % 3;
            uint32_t aS = sbase + (uint32_t)st * 32768u;
            uint32_t bS = aS + 16384u;
            const char* Ap = gA + (size_t)(c + 2) * 128;
            const char* Bp = gB + (size_t)(c + 2) * 128;
            #pragma unroll
            for (int i = 0; i < 4; i++) {
                CP_ASYNC16(aS + sts[i], Ap + i * 16);
                CP_ASYNC16(bS + sts[i], Bp + i * 16);
            }
            CP_COMMIT();
        }
        int cst = c % 3;
        uint32_t aS = sbase + (uint32_t)cst * 32768u;
        uint32_t bS = aS + 16384u;
        #pragma unroll
        for (int kq = 0; kq < 4; kq++) {
            uint32_t kb = (uint32_t)kq * 32u;
            uint32_t afr[2][4];
            #pragma unroll
            for (int mt = 0; mt < 2; mt++)
                LDSM_X4(afr[mt][0], afr[mt][1], afr[mt][2], afr[mt][3],
                        aS + a_row[mt] + ((a_cb + kb) ^ a_rx[mt]));
            uint32_t bfr[4][4];
            #pragma unroll
            for (int nt4 = 0; nt4 < 4; nt4++)
                LDSM_X4(bfr[nt4][0], bfr[nt4][1], bfr[nt4][2], bfr[nt4][3],
                        bS + b_row[nt4] + ((b_cb + kb) ^ b_rx[nt4]));
            #pragma unroll
            for (int mt = 0; mt < 2; mt++)
                #pragma unroll
                for (int nt = 0; nt < 8; nt++)
                    hmma16816(acc[mt][nt], afr[mt], &bfr[nt >> 1][(nt & 1) * 2]);
        }
    }

    // epilogue
    int g2 = lane >> 2, t2 = lane & 3;
    #pragma unroll
    for (int mt = 0; mt < 2; mt++) {
        #pragma unroll
        for (int nt = 0; nt < 8; nt++) {
            int row0 = brow + wm * 32 + mt * 16 + g2;
            int col = bcol + wn * 64 + nt * 8 + t2 * 2;
            float2 v0 = make_float2(acc[mt][nt][0], acc[mt][nt][1]);
            float2 v1 = make_float2(acc[mt][nt][2], acc[mt][nt][3]);
            *(float2*)(C + (size_t)row0 * K + col) = v0;
            *(float2*)(C + (size_t)(row0 + 8) * K + col) = v1;
        }
    }
}

// =======================================================================
// Kernel 5: combine Karatsuba outputs (+bias), rotate back, write out
// =======================================================================
__global__ __launch_bounds__(256) void scatter_rot_kernel(const float* __restrict__ fc0_b,
                                                          float* __restrict__ out) {
    int n = blockIdx.x;
    __shared__ float pre[DIMX];
    __shared__ float dt[164];
    for (int c = threadIdx.x; c < 164; c += 256) dt[c] = g_DT[(size_t)n * 164 + c];

    for (int j = threadIdx.x; j < 640; j += 256) {
        int l = j >> 7, k = j & 127;
        pre[128*l*l + k*(2*l + 1) + l] = g_Z[(size_t)n * 640 + j] + fc0_b[j];
    }
    #define SCAT(MM, CO, P0, P1, P2)                                         \
    for (int t = threadIdx.x; t < CO; t += 256) {                            \
        float v1 = g_Z[(size_t)NS * P0 + (size_t)n * CO + t];                \
        float v2 = g_Z[(size_t)NS * P1 + (size_t)n * CO + t];                \
        float v3 = g_Z[(size_t)NS * P2 + (size_t)n * CO + t];                \
        float re = v1 - v2, im = v3 - v1 - v2;                               \
        int c0 = t & 1, ph = t >> 1;                                         \
        int p1 = (CO >> 1) + ph;                                             \
        int l0 = MM + (ph >> 7), k0 = ph & 127;                              \
        int l1 = MM + (p1 >> 7), k1 = p1 & 127;                              \
        int i0 = c0 ? (l0 + MM) : (l0 - MM);                                 \
        int i1 = c0 ? (l1 + MM) : (l1 - MM);                                 \
        pre[128*l0*l0 + k0*(2*l0 + 1) + i0] = re;                            \
        pre[128*l1*l1 + k1*(2*l1 + 1) + i1] = im;                            \
    }
    SCAT(1, 512, 640, 1152, 1664)
    SCAT(2, 384, 2176, 2560, 2944)
    SCAT(3, 256, 3328, 3584, 3840)
    SCAT(4, 128, 4096, 4224, 4352)
    __syncthreads();

    float* orow = out + (size_t)n * DIMX;
    for (int c = threadIdx.x; c < 128; c += 256) orow[c] = pre[c];

    // block-per-thread inverse rotation
    int k = threadIdx.x & 127;
    int h = threadIdx.x >> 7;
    #define ROTO(D, DTO, XO) do {                                            \
        const float* pb = pre + XO + k * D;                                  \
        float xv[D];                                                         \
        _Pragma("unroll") for (int j = 0; j < D; j++) xv[j] = pb[j];         \
        _Pragma("unroll") for (int i = 0; i < D; i++) {                      \
            const float* ddp = dt + DTO + i * D;                             \
            float v = 0.f;                                                   \
            _Pragma("unroll") for (int j = 0; j < D; j++) v += ddp[j] * xv[j]; \
            orow[XO + k * D + i] = v;                                        \
        }                                                                    \
    } while (0)
    if (h == 0) { ROTO(3, 0, 128);  ROTO(9, 83, 2048); }
    else        { ROTO(5, 9, 512);  ROTO(7, 34, 1152); }
}

// =======================================================================
// launch
// =======================================================================
extern "C" void kernel_launch(void* const* d_in, const int* in_sizes, int n_in,
                              void* d_out, int out_size) {
    const float* x     = (const float*)d_in[0];
    const float* R     = (const float*)d_in[1];
    const float* fc0_w = (const float*)d_in[2];
    const float* fc0_b = (const float*)d_in[3];
    const float* w1    = (const float*)d_in[4];
    const float* w2    = (const float*)d_in[5];
    const float* w3    = (const float*)d_in[6];
    const float* w4    = (const float*)d_in[7];
    float* out = (float*)d_out;

    build_J_kernel<<<1, 384>>>();
    build_w_kernel<<<(1884160 + 255) / 256, 256>>>(fc0_w, w1, w2, w3, w4);
    wigner_kernel<<<(NS * 4 + 127) / 128, 128>>>(R);
    rot_gather_kernel<<<NS, 256>>>(x);

    cudaFuncSetAttribute(hmma_gemm_all_kernel,
                         cudaFuncAttributeMaxDynamicSharedMemorySize, 98304);
    hmma_gemm_all_kernel<<<4480, 256, 98304>>>();

    scatter_rot_kernel<<<NS, 256>>>(fc0_b, out);
}

// round 8
// speedup vs baseline: 1.0093x; 1.0093x over previous
#include <cuda_runtime.h>
#include <cuda_fp16.h>
#include <math.h>
#include <stdint.h>

// ---------------- problem constants ----------------
#define NS    16384
#define DIMX  3200
#define LMAX  4

__constant__ int c_offD[4] = {0, 9, 34, 83};

// 13 sub-GEMMs: 0: m0 (N=640, K=512 — l=0 input block is exactly zero, dropped);
// then per m=1..4: A, B, A+B (co x co), co = {512, 384, 256, 128}
__constant__ int cg_tileStart[14] = {0,640,1152,1664,2176,2560,2944,3328,3584,3840,4096,4224,4352,4480};
__constant__ int cg_Ksub[13]  = {512,512,512,512,384,384,384,256,256,256,128,128,128};
__constant__ int cg_Nsub[13]  = {640,512,512,512,384,384,384,256,256,256,128,128,128};
__constant__ int cg_Up[13]    = {0,512,1024,1536,2048,2432,2816,3200,3456,3712,3968,4096,4224};   // U prefixes (total 4352)
__constant__ int cg_Zp[13]    = {0,640,1152,1664,2176,2560,2944,3328,3584,3840,4096,4224,4352};   // Z prefixes (total 4480)
__constant__ int cg_Wpref[14] = {0,327680,589824,851968,1114112,1261568,1409024,1556480,1622016,1687552,1753088,1769472,1785856,1802240};

// ---------------- device scratch ----------------
__device__ float g_J[164];
__device__ float g_DT[(size_t)NS * 164];
__device__ __half g_W[1802240];
__device__ __half g_U[(size_t)NS * 4352];
__device__ float g_Z[(size_t)NS * 4480];

// =======================================================================
// Kernel 0: build J matrices (reference algorithm, fp64, parallel)
// =======================================================================
__global__ void build_J_kernel() {
    __shared__ double Xr[4][81], Xi[4][81], Qr[4][81], Qi[4][81];
    __shared__ double Sa[4][81], Se[4][81], St[4][81];
    int g = threadIdx.x / 96;
    int e = threadIdx.x % 96;
    int l = g + 1, d = 2*l + 1, dd = d*d;
    const double j = (double)l;
    const double SQ12 = 0.70710678118654752440;
    const double PI_D = 3.14159265358979323846;

    if (e < 81) { Xr[g][e]=0; Xi[g][e]=0; Qr[g][e]=0; Qi[g][e]=0; }
    __syncthreads();
    if (e == 0) {
        for (int i2 = 0; i2 < d-1; i2++) {
            double m  = -j + (double)i2;
            double rv = -sqrt(j*(j+1.0) - m*(m+1.0));
            Xr[g][(i2+1)*d + i2] += 0.5 * rv;
            double m2 = -j + 1.0 + (double)i2;
            double lv = sqrt(j*(j+1.0) - m2*(m2-1.0));
            Xr[g][i2*d + (i2+1)] += 0.5 * lv;
        }
        for (int i2 = 0; i2 < d; i2++) Xi[g][i2*d + i2] += (-j + (double)i2);
        for (int m = 1; m <= l; m++) {
            int r = l - m;
            Qr[g][r*d + (l+m)] = SQ12;
            Qi[g][r*d + r]     = -SQ12;
            int r2 = l + m;
            double sgn = (m & 1) ? -1.0 : 1.0;
            Qr[g][r2*d + r2]     = sgn * SQ12;
            Qi[g][r2*d + (l-m)]  = sgn * SQ12;
        }
        Qr[g][l*d + l] = 1.0;
    }
    __syncthreads();
    if (e < dd) {
        int i = e / d, jj = e % d;
        double s = 0.0;
        for (int k = 0; k < d; k++) {
            double mr = 0.0, mi = 0.0;
            for (int p = 0; p < d; p++) {
                mr += Xr[g][k*d+p]*Qr[g][p*d+jj] - Xi[g][k*d+p]*Qi[g][p*d+jj];
                mi += Xr[g][k*d+p]*Qi[g][p*d+jj] + Xi[g][k*d+p]*Qr[g][p*d+jj];
            }
            s += Qr[g][k*d+i]*mr + Qi[g][k*d+i]*mi;
        }
        Sa[g][e] = (PI_D * SQ12) * s * (1.0/1024.0);
        Se[g][e] = (i == jj) ? 1.0 : 0.0;
        St[g][e] = (i == jj) ? 1.0 : 0.0;
    }
    __syncthreads();
    for (int k = 1; k < 24; k++) {
        double v = 0.0;
        if (e < dd) {
            int i = e / d, jj = e % d;
            double s = 0.0;
            for (int p = 0; p < d; p++) s += St[g][i*d+p] * Sa[g][p*d+jj];
            v = s / (double)k;
        }
        __syncthreads();
        if (e < dd) { St[g][e] = v; Se[g][e] += v; }
        __syncthreads();
    }
    for (int s2 = 0; s2 < 10; s2++) {
        double v = 0.0;
        if (e < dd) {
            int i = e / d, jj = e % d;
            double s = 0.0;
            for (int p = 0; p < d; p++) s += Se[g][i*d+p] * Se[g][p*d+jj];
            v = s;
        }
        __syncthreads();
        if (e < dd) Se[g][e] = v;
        __syncthreads();
    }
    if (e < dd) g_J[c_offD[g] + e] = (float)Se[g][e];
}

// =======================================================================
// Kernel 1: build W (fp16): sub 0 = fc0_w cols 128..639; subs 3m-2..3m: A, B, A+B
// =======================================================================
__global__ void build_w_kernel(const float* __restrict__ fc0_w,
                               const float* __restrict__ w1, const float* __restrict__ w2,
                               const float* __restrict__ w3, const float* __restrict__ w4) {
    int gid = blockIdx.x * blockDim.x + threadIdx.x;
    if (gid >= 1802240) return;
    int s = 0;
    #pragma unroll
    for (int q = 1; q < 13; q++) if (gid >= cg_Wpref[q]) s = q;
    int local = gid - cg_Wpref[s];
    int K = cg_Ksub[s];
    int o = local / K;
    int t = local - o * K;
    float v;
    if (s == 0) {
        v = fc0_w[o * 640 + t + 128];   // skip zero l=0 K-block
    } else {
        int m = (s - 1) / 3 + 1;
        int which = (s - 1) % 3;
        const float* w = (m == 1) ? w1 : (m == 2) ? w2 : (m == 3) ? w3 : w4;
        if (which == 0)      v = w[o * K + t];
        else if (which == 1) v = w[(K + o) * K + t];
        else                 v = w[o * K + t] + w[(K + o) * K + t];
    }
    g_W[gid] = __float2half_rn(v);
}

// =======================================================================
// Kernel 2: per-sample Wigner D^T (D = Z(a) J Z(b) J)
// =======================================================================
__global__ void wigner_kernel(const float* __restrict__ R) {
    int gid = blockIdx.x * blockDim.x + threadIdx.x;
    if (gid >= NS * 4) return;
    int n = gid >> 2;
    int l = (gid & 3) + 1;
    int d = 2*l + 1;

    float vx = R[n*3 + 1], vy = R[n*3 + 2], vz = R[n*3 + 0];
    float nrm = sqrtf(vx*vx + vy*vy + vz*vz);
    nrm = fmaxf(nrm, 1e-12f);
    vx /= nrm; vy /= nrm; vz /= nrm;
    vx = fminf(fmaxf(vx, -1.f), 1.f);
    vy = fminf(fmaxf(vy, -1.f), 1.f);
    vz = fminf(fmaxf(vz, -1.f), 1.f);
    float beta  = acosf(vy);
    float alpha = atan2f(vx, vz);

    const float* J = g_J + c_offD[l-1];
    float T1[81], T2[81], Dm[81];

    for (int i = 0; i < d; i++) {
        float fr = (float)(l - i);
        float c = cosf(fr * beta), s = sinf(fr * beta);
        int ri = d - 1 - i;
        for (int jj = 0; jj < d; jj++)
            T1[i*d + jj] = c * J[i*d + jj] + s * J[ri*d + jj];
    }
    for (int i = 0; i < d; i++)
        for (int jj = 0; jj < d; jj++) {
            float s = 0.f;
            for (int k = 0; k < d; k++) s += J[i*d + k] * T1[k*d + jj];
            T2[i*d + jj] = s;
        }
    for (int i = 0; i < d; i++) {
        float fr = (float)(l - i);
        float c = cosf(fr * alpha), s = sinf(fr * alpha);
        int ri = d - 1 - i;
        for (int jj = 0; jj < d; jj++)
            Dm[i*d + jj] = c * T2[i*d + jj] + s * T2[ri*d + jj];
    }
    float* dst = g_DT + (size_t)n * 164 + c_offD[l-1];
    for (int i = 0; i < d; i++)
        for (int jj = 0; jj < d; jj++)
            dst[i*d + jj] = Dm[jj*d + i];
}

// =======================================================================
// Kernel 3: rotate x (block-per-thread), gather into fp16 sub-GEMM inputs
// =======================================================================
__global__ __launch_bounds__(256) void rot_gather_kernel(const float* __restrict__ x) {
    int n = blockIdx.x;
    __shared__ float xs[DIMX];
    __shared__ float xrot[DIMX];
    __shared__ float dt[164];
    const float* xr = x + (size_t)n * DIMX;
    for (int c = threadIdx.x; c < DIMX; c += 256) xs[c] = xr[c];
    for (int c = threadIdx.x; c < 164; c += 256) dt[c] = g_DT[(size_t)n * 164 + c];
    __syncthreads();

    // phase 1: block-per-thread rotation. k = tid&127; half 0: l=1,4; half 1: l=2,3
    int k = threadIdx.x & 127;
    int h = threadIdx.x >> 7;
    #define ROTBLK(D, DTO, XO) do {                                          \
        const float* xb = xs + XO + k * D;                                   \
        float xv[D];                                                         \
        _Pragma("unroll") for (int j = 0; j < D; j++) xv[j] = xb[j];         \
        _Pragma("unroll") for (int i = 0; i < D; i++) {                      \
            const float* ddp = dt + DTO + i * D;                             \
            float v = 0.f;                                                   \
            _Pragma("unroll") for (int j = 0; j < D; j++) v += ddp[j] * xv[j]; \
            xrot[XO + k * D + i] = v;                                        \
        }                                                                    \
    } while (0)
    if (h == 0) { ROTBLK(3, 0, 128);  ROTBLK(9, 83, 2048); }
    else        { ROTBLK(5, 9, 512);  ROTBLK(7, 34, 1152); }
    __syncthreads();

    // phase 2: gather into U (m0 block: only l=1..4 diagonal entries, 512 wide)
    for (int j = threadIdx.x; j < 512; j += 256) {
        int jj = j + 128;
        int l = jj >> 7, kk = jj & 127;
        g_U[(size_t)n * 512 + j] = __float2half_rn(xrot[128*l*l + kk*(2*l + 1) + l]);
    }
    #define GATH(MM, CO, P0, P1, P2)                                         \
    for (int t = threadIdx.x; t < CO; t += 256) {                            \
        int c0 = t & 1, ph = t >> 1;                                         \
        int p1 = (CO >> 1) + ph;                                             \
        int l0 = MM + (ph >> 7), k0 = ph & 127;                              \
        int l1 = MM + (p1 >> 7), k1 = p1 & 127;                              \
        int i0 = c0 ? (l0 + MM) : (l0 - MM);                                 \
        int i1 = c0 ? (l1 + MM) : (l1 - MM);                                 \
        float u0 = xrot[128*l0*l0 + k0*(2*l0 + 1) + i0];                     \
        float u1 = xrot[128*l1*l1 + k1*(2*l1 + 1) + i1];                     \
        g_U[(size_t)NS * P0 + (size_t)n * CO + t] = __float2half_rn(u0);     \
        g_U[(size_t)NS * P1 + (size_t)n * CO + t] = __float2half_rn(u1);     \
        g_U[(size_t)NS * P2 + (size_t)n * CO + t] = __float2half_rn(u0 + u1);\
    }
    GATH(1, 512, 512, 1024, 1536)
    GATH(2, 384, 2048, 2432, 2816)
    GATH(3, 256, 3200, 3456, 3712)
    GATH(4, 128, 3968, 4096, 4224)
}

// =======================================================================
// Kernel 4: HMMA fp16 GEMM over 13 sub-GEMMs (C[NxK tiles], K chunks 64)
// =======================================================================
__device__ __forceinline__ uint32_t smem_u32(const void* p) {
    uint32_t a;
    asm("{ .reg .u64 t; cvta.to.shared.u64 t, %1; cvt.u32.u64 %0, t; }" : "=r"(a) : "l"(p));
    return a;
}
#define CP_ASYNC16(dst, src) \
    asm volatile("cp.async.cg.shared.global [%0], [%1], 16;" :: "r"(dst), "l"(src) : "memory")
#define CP_COMMIT() asm volatile("cp.async.commit_group;" ::: "memory")
#define CP_WAIT1()  asm volatile("cp.async.wait_group 1;" ::: "memory")
#define CP_WAIT0()  asm volatile("cp.async.wait_group 0;" ::: "memory")
#define LDSM_X4(r0, r1, r2, r3, addr) \
    asm volatile("ldmatrix.sync.aligned.m8n8.x4.shared.b16 {%0,%1,%2,%3}, [%4];" \
                 : "=r"(r0), "=r"(r1), "=r"(r2), "=r"(r3) : "r"(addr))

__device__ __forceinline__ void hmma16816(float* c, const uint32_t* a, const uint32_t* b) {
    asm volatile(
        "mma.sync.aligned.m16n8k16.row.col.f32.f16.f16.f32 "
        "{%0,%1,%2,%3}, {%4,%5,%6,%7}, {%8,%9}, {%0,%1,%2,%3};"
        : "+f"(c[0]), "+f"(c[1]), "+f"(c[2]), "+f"(c[3])
        : "r"(a[0]), "r"(a[1]), "r"(a[2]), "r"(a[3]), "r"(b[0]), "r"(b[1]));
}

__global__ __launch_bounds__(256) void hmma_gemm_all_kernel() {
    extern __shared__ __align__(1024) char dsm[];
    uint32_t sbase = smem_u32(dsm);

    int tid = threadIdx.x;
    int wid = tid >> 5;
    int lane = tid & 31;

    // ---- tile decode ----
    int id = blockIdx.x;
    int s = 0;
    #pragma unroll
    for (int q = 1; q < 13; q++) if (id >= cg_tileStart[q]) s = q;
    int local = id - cg_tileStart[s];
    int K = cg_Ksub[s];
    int N = cg_Nsub[s];
    int gx = N >> 7;
    int bcolt = local % gx, browt = local / gx;
    int brow = browt << 7, bcol = bcolt << 7;

    const __half* A = g_U + (size_t)NS * cg_Up[s];
    const __half* B = g_W + cg_Wpref[s];
    float* C = g_Z + (size_t)NS * cg_Zp[s];

    // ---- global->smem: 2 threads/row, 4x16B each ----
    int r = tid >> 1, q2 = tid & 1;
    const char* gA = (const char*)(A + (size_t)(brow + r) * K + q2 * 32);
    const char* gB = (const char*)(B + (size_t)(bcol + r) * K + q2 * 32);
    uint32_t sts[4];
    #pragma unroll
    for (int i = 0; i < 4; i++) {
        uint32_t off = (uint32_t)r * 128u + (uint32_t)(q2 * 4 + i) * 16u;
        sts[i] = off ^ ((off >> 3) & 0x70);
    }

    // ---- per-warp compute layout ----
    int wm = wid >> 1, wn = wid & 1;
    uint32_t a_row[2], a_rx[2];
    #pragma unroll
    for (int mt = 0; mt < 2; mt++) {
        int row = wm * 32 + mt * 16 + (lane & 15);
        a_row[mt] = (uint32_t)row * 128u;
        a_rx[mt] = (uint32_t)(row & 7) << 4;
    }
    uint32_t a_cb = ((lane >> 4) & 1) * 16u;
    int nloc = (lane & 7) + ((lane & 16) >> 1);
    uint32_t b_row[4], b_rx[4];
    #pragma unroll
    for (int nt4 = 0; nt4 < 4; nt4++) {
        int nrow = wn * 64 + nt4 * 16 + nloc;
        b_row[nt4] = (uint32_t)nrow * 128u;
        b_rx[nt4] = (uint32_t)(nrow & 7) << 4;
    }
    uint32_t b_cb = ((lane >> 3) & 1) * 16u;

    float acc[2][8][4];
    #pragma unroll
    for (int mt = 0; mt < 2; mt++)
        #pragma unroll
        for (int nt = 0; nt < 8; nt++)
            #pragma unroll
            for (int e = 0; e < 4; e++) acc[mt][nt][e] = 0.f;

    int NC = K >> 6;

    // prologue: chunks 0,1 into stages 0,1
    #pragma unroll
    for (int p = 0; p < 2; p++) {
        uint32_t aS = sbase + (uint32_t)p * 32768u;
        uint32_t bS = aS + 16384u;
        const char* Ap = gA + (size_t)p * 128;
        const char* Bp = gB + (size_t)p * 128;
        #pragma unroll
        for (int i = 0; i < 4; i++) {
            CP_ASYNC16(aS + sts[i], Ap + i * 16);
            CP_ASYNC16(bS + sts[i], Bp + i * 16);
        }
        CP_COMMIT();
    }

    for (int c = 0; c < NC; ++c) {
        if (c + 1 < NC) CP_WAIT1(); else CP_WAIT0();
        __syncthreads();
        if (c + 2 < NC) {
            int st = (c + 2) % 3;
            uint32_t aS = sbase + (uint32_t)st * 32768u;
            uint32_t bS = aS + 16384u;
            const char* Ap = gA + (size_t)(c + 2) * 128;
            const char* Bp = gB + (size_t)(c + 2) * 128;
            #pragma unroll
            for (int i = 0; i < 4; i++) {
                CP_ASYNC16(aS + sts[i], Ap + i * 16);
                CP_ASYNC16(bS + sts[i], Bp + i * 16);
            }
            CP_COMMIT();
        }
        int cst = c % 3;
        uint32_t aS = sbase + (uint32_t)cst * 32768u;
        uint32_t bS = aS + 16384u;
        #pragma unroll
        for (int kq = 0; kq < 4; kq++) {
            uint32_t kb = (uint32_t)kq * 32u;
            uint32_t afr[2][4];
            #pragma unroll
            for (int mt = 0; mt < 2; mt++)
                LDSM_X4(afr[mt][0], afr[mt][1], afr[mt][2], afr[mt][3],
                        aS + a_row[mt] + ((a_cb + kb) ^ a_rx[mt]));
            uint32_t bfr[4][4];
            #pragma unroll
            for (int nt4 = 0; nt4 < 4; nt4++)
                LDSM_X4(bfr[nt4][0], bfr[nt4][1], bfr[nt4][2], bfr[nt4][3],
                        bS + b_row[nt4] + ((b_cb + kb) ^ b_rx[nt4]));
            #pragma unroll
            for (int mt = 0; mt < 2; mt++)
                #pragma unroll
                for (int nt = 0; nt < 8; nt++)
                    hmma16816(acc[mt][nt], afr[mt], &bfr[nt >> 1][(nt & 1) * 2]);
        }
    }

    // epilogue (C row stride = N)
    int g2 = lane >> 2, t2 = lane & 3;
    #pragma unroll
    for (int mt = 0; mt < 2; mt++) {
        #pragma unroll
        for (int nt = 0; nt < 8; nt++) {
            int row0 = brow + wm * 32 + mt * 16 + g2;
            int col = bcol + wn * 64 + nt * 8 + t2 * 2;
            float2 v0 = make_float2(acc[mt][nt][0], acc[mt][nt][1]);
            float2 v1 = make_float2(acc[mt][nt][2], acc[mt][nt][3]);
            *(float2*)(C + (size_t)row0 * N + col) = v0;
            *(float2*)(C + (size_t)(row0 + 8) * N + col) = v1;
        }
    }
}

// =======================================================================
// Kernel 5: combine Karatsuba outputs (+bias), rotate back, write out
// =======================================================================
__global__ __launch_bounds__(256) void scatter_rot_kernel(const float* __restrict__ fc0_b,
                                                          float* __restrict__ out) {
    int n = blockIdx.x;
    __shared__ float pre[DIMX];
    __shared__ float dt[164];
    for (int c = threadIdx.x; c < 164; c += 256) dt[c] = g_DT[(size_t)n * 164 + c];

    for (int j = threadIdx.x; j < 640; j += 256) {
        int l = j >> 7, k = j & 127;
        pre[128*l*l + k*(2*l + 1) + l] = g_Z[(size_t)n * 640 + j] + fc0_b[j];
    }
    #define SCAT(MM, CO, P0, P1, P2)                                         \
    for (int t = threadIdx.x; t < CO; t += 256) {                            \
        float v1 = g_Z[(size_t)NS * P0 + (size_t)n * CO + t];                \
        float v2 = g_Z[(size_t)NS * P1 + (size_t)n * CO + t];                \
        float v3 = g_Z[(size_t)NS * P2 + (size_t)n * CO + t];                \
        float re = v1 - v2, im = v3 - v1 - v2;                               \
        int c0 = t & 1, ph = t >> 1;                                         \
        int p1 = (CO >> 1) + ph;                                             \
        int l0 = MM + (ph >> 7), k0 = ph & 127;                              \
        int l1 = MM + (p1 >> 7), k1 = p1 & 127;                              \
        int i0 = c0 ? (l0 + MM) : (l0 - MM);                                 \
        int i1 = c0 ? (l1 + MM) : (l1 - MM);                                 \
        pre[128*l0*l0 + k0*(2*l0 + 1) + i0] = re;                            \
        pre[128*l1*l1 + k1*(2*l1 + 1) + i1] = im;                            \
    }
    SCAT(1, 512, 640, 1152, 1664)
    SCAT(2, 384, 2176, 2560, 2944)
    SCAT(3, 256, 3328, 3584, 3840)
    SCAT(4, 128, 4096, 4224, 4352)
    __syncthreads();

    float* orow = out + (size_t)n * DIMX;
    for (int c = threadIdx.x; c < 128; c += 256) orow[c] = pre[c];

    // block-per-thread inverse rotation
    int k = threadIdx.x & 127;
    int h = threadIdx.x >> 7;
    #define ROTO(D, DTO, XO) do {                                            \
        const float* pb = pre + XO + k * D;                                  \
        float xv[D];                                                         \
        _Pragma("unroll") for (int j = 0; j < D; j++) xv[j] = pb[j];         \
        _Pragma("unroll") for (int i = 0; i < D; i++) {                      \
            const float* ddp = dt + DTO + i * D;                             \
            float v = 0.f;                                                   \
            _Pragma("unroll") for (int j = 0; j < D; j++) v += ddp[j] * xv[j]; \
            orow[XO + k * D + i] = v;                                        \
        }                                                                    \
    } while (0)
    if (h == 0) { ROTO(3, 0, 128);  ROTO(9, 83, 2048); }
    else        { ROTO(5, 9, 512);  ROTO(7, 34, 1152); }
}

// =======================================================================
// launch
// =======================================================================
extern "C" void kernel_launch(void* const* d_in, const int* in_sizes, int n_in,
                              void* d_out, int out_size) {
    const float* x     = (const float*)d_in[0];
    const float* R     = (const float*)d_in[1];
    const float* fc0_w = (const float*)d_in[2];
    const float* fc0_b = (const float*)d_in[3];
    const float* w1    = (const float*)d_in[4];
    const float* w2    = (const float*)d_in[5];
    const float* w3    = (const float*)d_in[6];
    const float* w4    = (const float*)d_in[7];
    float* out = (float*)d_out;

    build_J_kernel<<<1, 384>>>();
    build_w_kernel<<<(1802240 + 255) / 256, 256>>>(fc0_w, w1, w2, w3, w4);
    wigner_kernel<<<(NS * 4 + 127) / 128, 128>>>(R);
    rot_gather_kernel<<<NS, 256>>>(x);

    cudaFuncSetAttribute(hmma_gemm_all_kernel,
                         cudaFuncAttributeMaxDynamicSharedMemorySize, 98304);
    hmma_gemm_all_kernel<<<4480, 256, 98304>>>();

    scatter_rot_kernel<<<NS, 256>>>(fc0_b, out);
}

// round 9
// speedup vs baseline: 1.1171x; 1.1068x over previous
#include <cuda_runtime.h>
#include <cuda_fp16.h>
#include <math.h>
#include <stdint.h>

// ---------------- problem constants ----------------
#define NS    16384
#define DIMX  3200
#define LMAX  4

__constant__ int c_offD[4] = {0, 9, 34, 83};

// 13 sub-GEMMs: 0: m0 (N=640, K=512 — l=0 input block is exactly zero, dropped);
// then per m=1..4: A, B, A+B (co x co), co = {512, 384, 256, 128}
__constant__ int cg_tileStart[14] = {0,640,1152,1664,2176,2560,2944,3328,3584,3840,4096,4224,4352,4480};
__constant__ int cg_Ksub[13]  = {512,512,512,512,384,384,384,256,256,256,128,128,128};
__constant__ int cg_Nsub[13]  = {640,512,512,512,384,384,384,256,256,256,128,128,128};
__constant__ int cg_Up[13]    = {0,512,1024,1536,2048,2432,2816,3200,3456,3712,3968,4096,4224};   // U prefixes (total 4352)
__constant__ int cg_Zp[13]    = {0,640,1152,1664,2176,2560,2944,3328,3584,3840,4096,4224,4352};   // Z prefixes (total 4480)
__constant__ int cg_Wpref[14] = {0,327680,589824,851968,1114112,1261568,1409024,1556480,1622016,1687552,1753088,1769472,1785856,1802240};

// ---------------- device scratch ----------------
__device__ float g_J[164];
__device__ float g_DT[(size_t)NS * 164];
__device__ __half g_W[1802240];
__device__ __half g_U[(size_t)NS * 4352];
__device__ float g_Z[(size_t)NS * 4480];

// =======================================================================
// Kernel 0: build J matrices (reference algorithm, fp64, parallel)
// =======================================================================
__global__ void build_J_kernel() {
    __shared__ double Xr[4][81], Xi[4][81], Qr[4][81], Qi[4][81];
    __shared__ double Sa[4][81], Se[4][81], St[4][81];
    int g = threadIdx.x / 96;
    int e = threadIdx.x % 96;
    int l = g + 1, d = 2*l + 1, dd = d*d;
    const double j = (double)l;
    const double SQ12 = 0.70710678118654752440;
    const double PI_D = 3.14159265358979323846;

    if (e < 81) { Xr[g][e]=0; Xi[g][e]=0; Qr[g][e]=0; Qi[g][e]=0; }
    __syncthreads();
    if (e == 0) {
        for (int i2 = 0; i2 < d-1; i2++) {
            double m  = -j + (double)i2;
            double rv = -sqrt(j*(j+1.0) - m*(m+1.0));
            Xr[g][(i2+1)*d + i2] += 0.5 * rv;
            double m2 = -j + 1.0 + (double)i2;
            double lv = sqrt(j*(j+1.0) - m2*(m2-1.0));
            Xr[g][i2*d + (i2+1)] += 0.5 * lv;
        }
        for (int i2 = 0; i2 < d; i2++) Xi[g][i2*d + i2] += (-j + (double)i2);
        for (int m = 1; m <= l; m++) {
            int r = l - m;
            Qr[g][r*d + (l+m)] = SQ12;
            Qi[g][r*d + r]     = -SQ12;
            int r2 = l + m;
            double sgn = (m & 1) ? -1.0 : 1.0;
            Qr[g][r2*d + r2]     = sgn * SQ12;
            Qi[g][r2*d + (l-m)]  = sgn * SQ12;
        }
        Qr[g][l*d + l] = 1.0;
    }
    __syncthreads();
    if (e < dd) {
        int i = e / d, jj = e % d;
        double s = 0.0;
        for (int k = 0; k < d; k++) {
            double mr = 0.0, mi = 0.0;
            for (int p = 0; p < d; p++) {
                mr += Xr[g][k*d+p]*Qr[g][p*d+jj] - Xi[g][k*d+p]*Qi[g][p*d+jj];
                mi += Xr[g][k*d+p]*Qi[g][p*d+jj] + Xi[g][k*d+p]*Qr[g][p*d+jj];
            }
            s += Qr[g][k*d+i]*mr + Qi[g][k*d+i]*mi;
        }
        Sa[g][e] = (PI_D * SQ12) * s * (1.0/1024.0);
        Se[g][e] = (i == jj) ? 1.0 : 0.0;
        St[g][e] = (i == jj) ? 1.0 : 0.0;
    }
    __syncthreads();
    for (int k = 1; k < 24; k++) {
        double v = 0.0;
        if (e < dd) {
            int i = e / d, jj = e % d;
            double s = 0.0;
            for (int p = 0; p < d; p++) s += St[g][i*d+p] * Sa[g][p*d+jj];
            v = s / (double)k;
        }
        __syncthreads();
        if (e < dd) { St[g][e] = v; Se[g][e] += v; }
        __syncthreads();
    }
    for (int s2 = 0; s2 < 10; s2++) {
        double v = 0.0;
        if (e < dd) {
            int i = e / d, jj = e % d;
            double s = 0.0;
            for (int p = 0; p < d; p++) s += Se[g][i*d+p] * Se[g][p*d+jj];
            v = s;
        }
        __syncthreads();
        if (e < dd) Se[g][e] = v;
        __syncthreads();
    }
    if (e < dd) g_J[c_offD[g] + e] = (float)Se[g][e];
}

// =======================================================================
// Kernel 1: build W (fp16): sub 0 = fc0_w cols 128..639; subs 3m-2..3m: A, B, A+B
// =======================================================================
__global__ void build_w_kernel(const float* __restrict__ fc0_w,
                               const float* __restrict__ w1, const float* __restrict__ w2,
                               const float* __restrict__ w3, const float* __restrict__ w4) {
    int gid = blockIdx.x * blockDim.x + threadIdx.x;
    if (gid >= 1802240) return;
    int s = 0;
    #pragma unroll
    for (int q = 1; q < 13; q++) if (gid >= cg_Wpref[q]) s = q;
    int local = gid - cg_Wpref[s];
    int K = cg_Ksub[s];
    int o = local / K;
    int t = local - o * K;
    float v;
    if (s == 0) {
        v = fc0_w[o * 640 + t + 128];   // skip zero l=0 K-block
    } else {
        int m = (s - 1) / 3 + 1;
        int which = (s - 1) % 3;
        const float* w = (m == 1) ? w1 : (m == 2) ? w2 : (m == 3) ? w3 : w4;
        if (which == 0)      v = w[o * K + t];
        else if (which == 1) v = w[(K + o) * K + t];
        else                 v = w[o * K + t] + w[(K + o) * K + t];
    }
    g_W[gid] = __float2half_rn(v);
}

// =======================================================================
// Kernel 2: per-sample Wigner D^T (D = Z(a) J Z(b) J)
// =======================================================================
__global__ void wigner_kernel(const float* __restrict__ R) {
    int gid = blockIdx.x * blockDim.x + threadIdx.x;
    if (gid >= NS * 4) return;
    int n = gid >> 2;
    int l = (gid & 3) + 1;
    int d = 2*l + 1;

    float vx = R[n*3 + 1], vy = R[n*3 + 2], vz = R[n*3 + 0];
    float nrm = sqrtf(vx*vx + vy*vy + vz*vz);
    nrm = fmaxf(nrm, 1e-12f);
    vx /= nrm; vy /= nrm; vz /= nrm;
    vx = fminf(fmaxf(vx, -1.f), 1.f);
    vy = fminf(fmaxf(vy, -1.f), 1.f);
    vz = fminf(fmaxf(vz, -1.f), 1.f);
    float beta  = acosf(vy);
    float alpha = atan2f(vx, vz);

    const float* J = g_J + c_offD[l-1];
    float T1[81], T2[81], Dm[81];

    for (int i = 0; i < d; i++) {
        float fr = (float)(l - i);
        float c = cosf(fr * beta), s = sinf(fr * beta);
        int ri = d - 1 - i;
        for (int jj = 0; jj < d; jj++)
            T1[i*d + jj] = c * J[i*d + jj] + s * J[ri*d + jj];
    }
    for (int i = 0; i < d; i++)
        for (int jj = 0; jj < d; jj++) {
            float s = 0.f;
            for (int k = 0; k < d; k++) s += J[i*d + k] * T1[k*d + jj];
            T2[i*d + jj] = s;
        }
    for (int i = 0; i < d; i++) {
        float fr = (float)(l - i);
        float c = cosf(fr * alpha), s = sinf(fr * alpha);
        int ri = d - 1 - i;
        for (int jj = 0; jj < d; jj++)
            Dm[i*d + jj] = c * T2[i*d + jj] + s * T2[ri*d + jj];
    }
    float* dst = g_DT + (size_t)n * 164 + c_offD[l-1];
    for (int i = 0; i < d; i++)
        for (int jj = 0; jj < d; jj++)
            dst[i*d + jj] = Dm[jj*d + i];
}

// =======================================================================
// Kernel 3: rotate x (block-per-thread), gather into fp16 sub-GEMM inputs
// =======================================================================
__global__ __launch_bounds__(256) void rot_gather_kernel(const float* __restrict__ x) {
    int n = blockIdx.x;
    __shared__ float xs[DIMX];
    __shared__ float xrot[DIMX];
    __shared__ float dt[164];
    const float* xr = x + (size_t)n * DIMX;
    for (int c = threadIdx.x; c < DIMX; c += 256) xs[c] = xr[c];
    for (int c = threadIdx.x; c < 164; c += 256) dt[c] = g_DT[(size_t)n * 164 + c];
    __syncthreads();

    // phase 1: block-per-thread rotation. k = tid&127; half 0: l=1,4; half 1: l=2,3
    int k = threadIdx.x & 127;
    int h = threadIdx.x >> 7;
    #define ROTBLK(D, DTO, XO) do {                                          \
        const float* xb = xs + XO + k * D;                                   \
        float xv[D];                                                         \
        _Pragma("unroll") for (int j = 0; j < D; j++) xv[j] = xb[j];         \
        _Pragma("unroll") for (int i = 0; i < D; i++) {                      \
            const float* ddp = dt + DTO + i * D;                             \
            float v = 0.f;                                                   \
            _Pragma("unroll") for (int j = 0; j < D; j++) v += ddp[j] * xv[j]; \
            xrot[XO + k * D + i] = v;                                        \
        }                                                                    \
    } while (0)
    if (h == 0) { ROTBLK(3, 0, 128);  ROTBLK(9, 83, 2048); }
    else        { ROTBLK(5, 9, 512);  ROTBLK(7, 34, 1152); }
    __syncthreads();

    // phase 2: gather into U (m0 block: only l=1..4 diagonal entries, 512 wide)
    for (int j = threadIdx.x; j < 512; j += 256) {
        int jj = j + 128;
        int l = jj >> 7, kk = jj & 127;
        g_U[(size_t)n * 512 + j] = __float2half_rn(xrot[128*l*l + kk*(2*l + 1) + l]);
    }
    #define GATH(MM, CO, P0, P1, P2)                                         \
    for (int t = threadIdx.x; t < CO; t += 256) {                            \
        int c0 = t & 1, ph = t >> 1;                                         \
        int p1 = (CO >> 1) + ph;                                             \
        int l0 = MM + (ph >> 7), k0 = ph & 127;                              \
        int l1 = MM + (p1 >> 7), k1 = p1 & 127;                              \
        int i0 = c0 ? (l0 + MM) : (l0 - MM);                                 \
        int i1 = c0 ? (l1 + MM) : (l1 - MM);                                 \
        float u0 = xrot[128*l0*l0 + k0*(2*l0 + 1) + i0];                     \
        float u1 = xrot[128*l1*l1 + k1*(2*l1 + 1) + i1];                     \
        g_U[(size_t)NS * P0 + (size_t)n * CO + t] = __float2half_rn(u0);     \
        g_U[(size_t)NS * P1 + (size_t)n * CO + t] = __float2half_rn(u1);     \
        g_U[(size_t)NS * P2 + (size_t)n * CO + t] = __float2half_rn(u0 + u1);\
    }
    GATH(1, 512, 512, 1024, 1536)
    GATH(2, 384, 2048, 2432, 2816)
    GATH(3, 256, 3200, 3456, 3712)
    GATH(4, 128, 3968, 4096, 4224)
}

// =======================================================================
// Kernel 4: HMMA fp16 GEMM over 13 sub-GEMMs (C[NxK tiles], K chunks 64)
// =======================================================================
__device__ __forceinline__ uint32_t smem_u32(const void* p) {
    uint32_t a;
    asm("{ .reg .u64 t; cvta.to.shared.u64 t, %1; cvt.u32.u64 %0, t; }" : "=r"(a) : "l"(p));
    return a;
}
#define CP_ASYNC16(dst, src) \
    asm volatile("cp.async.cg.shared.global [%0], [%1], 16;" :: "r"(dst), "l"(src) : "memory")
#define CP_COMMIT() asm volatile("cp.async.commit_group;" ::: "memory")
#define CP_WAIT1()  asm volatile("cp.async.wait_group 1;" ::: "memory")
#define CP_WAIT0()  asm volatile("cp.async.wait_group 0;" ::: "memory")
#define LDSM_X4(r0, r1, r2, r3, addr) \
    asm volatile("ldmatrix.sync.aligned.m8n8.x4.shared.b16 {%0,%1,%2,%3}, [%4];" \
                 : "=r"(r0), "=r"(r1), "=r"(r2), "=r"(r3) : "r"(addr))

__device__ __forceinline__ void hmma16816(float* c, const uint32_t* a, const uint32_t* b) {
    asm volatile(
        "mma.sync.aligned.m16n8k16.row.col.f32.f16.f16.f32 "
        "{%0,%1,%2,%3}, {%4,%5,%6,%7}, {%8,%9}, {%0,%1,%2,%3};"
        : "+f"(c[0]), "+f"(c[1]), "+f"(c[2]), "+f"(c[3])
        : "r"(a[0]), "r"(a[1]), "r"(a[2]), "r"(a[3]), "r"(b[0]), "r"(b[1]));
}

__global__ __launch_bounds__(256) void hmma_gemm_all_kernel() {
    extern __shared__ __align__(1024) char dsm[];
    uint32_t sbase = smem_u32(dsm);

    int tid = threadIdx.x;
    int wid = tid >> 5;
    int lane = tid & 31;

    // ---- tile decode ----
    int id = blockIdx.x;
    int s = 0;
    #pragma unroll
    for (int q = 1; q < 13; q++) if (id >= cg_tileStart[q]) s = q;
    int local = id - cg_tileStart[s];
    int K = cg_Ksub[s];
    int N = cg_Nsub[s];
    int gx = N >> 7;
    int bcolt = local % gx, browt = local / gx;
    int brow = browt << 7, bcol = bcolt << 7;

    const __half* A = g_U + (size_t)NS * cg_Up[s];
    const __half* B = g_W + cg_Wpref[s];
    float* C = g_Z + (size_t)NS * cg_Zp[s];

    // ---- global->smem: 2 threads/row, 4x16B each ----
    int r = tid >> 1, q2 = tid & 1;
    const char* gA = (const char*)(A + (size_t)(brow + r) * K + q2 * 32);
    const char* gB = (const char*)(B + (size_t)(bcol + r) * K + q2 * 32);
    uint32_t sts[4];
    #pragma unroll
    for (int i = 0; i < 4; i++) {
        uint32_t off = (uint32_t)r * 128u + (uint32_t)(q2 * 4 + i) * 16u;
        sts[i] = off ^ ((off >> 3) & 0x70);
    }

    // ---- per-warp compute layout ----
    int wm = wid >> 1, wn = wid & 1;
    uint32_t a_row[2], a_rx[2];
    #pragma unroll
    for (int mt = 0; mt < 2; mt++) {
        int row = wm * 32 + mt * 16 + (lane & 15);
        a_row[mt] = (uint32_t)row * 128u;
        a_rx[mt] = (uint32_t)(row & 7) << 4;
    }
    uint32_t a_cb = ((lane >> 4) & 1) * 16u;
    int nloc = (lane & 7) + ((lane & 16) >> 1);
    uint32_t b_row[4], b_rx[4];
    #pragma unroll
    for (int nt4 = 0; nt4 < 4; nt4++) {
        int nrow = wn * 64 + nt4 * 16 + nloc;
        b_row[nt4] = (uint32_t)nrow * 128u;
        b_rx[nt4] = (uint32_t)(nrow & 7) << 4;
    }
    uint32_t b_cb = ((lane >> 3) & 1) * 16u;

    float acc[2][8][4];
    #pragma unroll
    for (int mt = 0; mt < 2; mt++)
        #pragma unroll
        for (int nt = 0; nt < 8; nt++)
            #pragma unroll
            for (int e = 0; e < 4; e++) acc[mt][nt][e] = 0.f;

    int NC = K >> 6;

    // prologue: chunks 0,1 into stages 0,1
    #pragma unroll
    for (int p = 0; p < 2; p++) {
        uint32_t aS = sbase + (uint32_t)p * 32768u;
        uint32_t bS = aS + 16384u;
        const char* Ap = gA + (size_t)p * 128;
        const char* Bp = gB + (size_t)p * 128;
        #pragma unroll
        for (int i = 0; i < 4; i++) {
            CP_ASYNC16(aS + sts[i], Ap + i * 16);
            CP_ASYNC16(bS + sts[i], Bp + i * 16);
        }
        CP_COMMIT();
    }

    for (int c = 0; c < NC; ++c) {
        if (c + 1 < NC) CP_WAIT1(); else CP_WAIT0();
        __syncthreads();
        if (c + 2 < NC) {
            int st = (c + 2) % 3;
            uint32_t aS = sbase + (uint32_t)st * 32768u;
            uint32_t bS = aS + 16384u;
            const char* Ap = gA + (size_t)(c + 2) * 128;
            const char* Bp = gB + (size_t)(c + 2) * 128;
            #pragma unroll
            for (int i = 0; i < 4; i++) {
                CP_ASYNC16(aS + sts[i], Ap + i * 16);
                CP_ASYNC16(bS + sts[i], Bp + i * 16);
            }
            CP_COMMIT();
        }
        int cst = c % 3;
        uint32_t aS = sbase + (uint32_t)cst * 32768u;
        uint32_t bS = aS + 16384u;
        #pragma unroll
        for (int kq = 0; kq < 4; kq++) {
            uint32_t kb = (uint32_t)kq * 32u;
            uint32_t afr[2][4];
            #pragma unroll
            for (int mt = 0; mt < 2; mt++)
                LDSM_X4(afr[mt][0], afr[mt][1], afr[mt][2], afr[mt][3],
                        aS + a_row[mt] + ((a_cb + kb) ^ a_rx[mt]));
            uint32_t bfr[4][4];
            #pragma unroll
            for (int nt4 = 0; nt4 < 4; nt4++)
                LDSM_X4(bfr[nt4][0], bfr[nt4][1], bfr[nt4][2], bfr[nt4][3],
                        bS + b_row[nt4] + ((b_cb + kb) ^ b_rx[nt4]));
            #pragma unroll
            for (int mt = 0; mt < 2; mt++)
                #pragma unroll
                for (int nt = 0; nt < 8; nt++)
                    hmma16816(acc[mt][nt], afr[mt], &bfr[nt >> 1][(nt & 1) * 2]);
        }
    }

    // epilogue (C row stride = N)
    int g2 = lane >> 2, t2 = lane & 3;
    #pragma unroll
    for (int mt = 0; mt < 2; mt++) {
        #pragma unroll
        for (int nt = 0; nt < 8; nt++) {
            int row0 = brow + wm * 32 + mt * 16 + g2;
            int col = bcol + wn * 64 + nt * 8 + t2 * 2;
            float2 v0 = make_float2(acc[mt][nt][0], acc[mt][nt][1]);
            float2 v1 = make_float2(acc[mt][nt][2], acc[mt][nt][3]);
            *(float2*)(C + (size_t)row0 * N + col) = v0;
            *(float2*)(C + (size_t)(row0 + 8) * N + col) = v1;
        }
    }
}

// =======================================================================
// Kernel 5: combine Karatsuba outputs (+bias), rotate back (into shared),
//           then coalesced write out
// =======================================================================
__global__ __launch_bounds__(256) void scatter_rot_kernel(const float* __restrict__ fc0_b,
                                                          float* __restrict__ out) {
    int n = blockIdx.x;
    __shared__ float pre[DIMX];
    __shared__ float ob[DIMX];
    __shared__ float dt[164];
    for (int c = threadIdx.x; c < 164; c += 256) dt[c] = g_DT[(size_t)n * 164 + c];

    for (int j = threadIdx.x; j < 640; j += 256) {
        int l = j >> 7, k = j & 127;
        pre[128*l*l + k*(2*l + 1) + l] = g_Z[(size_t)n * 640 + j] + fc0_b[j];
    }
    #define SCAT(MM, CO, P0, P1, P2)                                         \
    for (int t = threadIdx.x; t < CO; t += 256) {                            \
        float v1 = g_Z[(size_t)NS * P0 + (size_t)n * CO + t];                \
        float v2 = g_Z[(size_t)NS * P1 + (size_t)n * CO + t];                \
        float v3 = g_Z[(size_t)NS * P2 + (size_t)n * CO + t];                \
        float re = v1 - v2, im = v3 - v1 - v2;                               \
        int c0 = t & 1, ph = t >> 1;                                         \
        int p1 = (CO >> 1) + ph;                                             \
        int l0 = MM + (ph >> 7), k0 = ph & 127;                              \
        int l1 = MM + (p1 >> 7), k1 = p1 & 127;                              \
        int i0 = c0 ? (l0 + MM) : (l0 - MM);                                 \
        int i1 = c0 ? (l1 + MM) : (l1 - MM);                                 \
        pre[128*l0*l0 + k0*(2*l0 + 1) + i0] = re;                            \
        pre[128*l1*l1 + k1*(2*l1 + 1) + i1] = im;                            \
    }
    SCAT(1, 512, 640, 1152, 1664)
    SCAT(2, 384, 2176, 2560, 2944)
    SCAT(3, 256, 3328, 3584, 3840)
    SCAT(4, 128, 4096, 4224, 4352)
    __syncthreads();

    // block-per-thread inverse rotation -> shared staging (conflict-free odd stride)
    int k = threadIdx.x & 127;
    int h = threadIdx.x >> 7;
    #define ROTO(D, DTO, XO) do {                                            \
        const float* pb = pre + XO + k * D;                                  \
        float xv[D];                                                         \
        _Pragma("unroll") for (int j = 0; j < D; j++) xv[j] = pb[j];         \
        _Pragma("unroll") for (int i = 0; i < D; i++) {                      \
            const float* ddp = dt + DTO + i * D;                             \
            float v = 0.f;                                                   \
            _Pragma("unroll") for (int j = 0; j < D; j++) v += ddp[j] * xv[j]; \
            ob[XO + k * D + i] = v;                                          \
        }                                                                    \
    } while (0)
    if (h == 0) {
        for (int c = threadIdx.x; c < 128; c += 128) ob[c] = pre[c];
        ROTO(3, 0, 128);  ROTO(9, 83, 2048);
    } else {
        ROTO(5, 9, 512);  ROTO(7, 34, 1152);
    }
    __syncthreads();

    // coalesced copy to global
    float* orow = out + (size_t)n * DIMX;
    for (int c = threadIdx.x; c < DIMX; c += 256) orow[c] = ob[c];
}

// =======================================================================
// launch
// =======================================================================
extern "C" void kernel_launch(void* const* d_in, const int* in_sizes, int n_in,
                              void* d_out, int out_size) {
    const float* x     = (const float*)d_in[0];
    const float* R     = (const float*)d_in[1];
    const float* fc0_w = (const float*)d_in[2];
    const float* fc0_b = (const float*)d_in[3];
    const float* w1    = (const float*)d_in[4];
    const float* w2    = (const float*)d_in[5];
    const float* w3    = (const float*)d_in[6];
    const float* w4    = (const float*)d_in[7];
    float* out = (float*)d_out;

    build_J_kernel<<<1, 384>>>();
    build_w_kernel<<<(1802240 + 255) / 256, 256>>>(fc0_w, w1, w2, w3, w4);
    wigner_kernel<<<(NS * 4 + 127) / 128, 128>>>(R);
    rot_gather_kernel<<<NS, 256>>>(x);

    cudaFuncSetAttribute(hmma_gemm_all_kernel,
                         cudaFuncAttributeMaxDynamicSharedMemorySize, 98304);
    hmma_gemm_all_kernel<<<4480, 256, 98304>>>();

    scatter_rot_kernel<<<NS, 256>>>(fc0_b, out);
}